// round 2
// baseline (speedup 1.0000x reference)
#include <cuda_runtime.h>
#include <math.h>

// Problem constants
#define B 64
#define C 256
#define H 56
#define W 56
#define HW (H * W)          // 3136
#define HW4 (HW / 4)        // 784 float4 per plane
#define R 16                // reduction ratio
#define PLANES (B * C)      // 16384
#define POSITION 205        // round(0.8 * 256)

// Scratch (allocation-free rule: use __device__ globals)
__device__ float g_y[B * C];      // GAP result
__device__ float g_mask[B * C];   // 0/1 mask

// ---------------------------------------------------------------------------
// Kernel 1: global average pool. One block per (b,c) plane.
// 256 threads, float4 loads, warp + smem reduce.
// ---------------------------------------------------------------------------
__global__ __launch_bounds__(256) void k1_gap(const float* __restrict__ x) {
    const int plane = blockIdx.x;
    const float4* __restrict__ px =
        reinterpret_cast<const float4*>(x + (size_t)plane * HW);
    const int tid = threadIdx.x;

    float acc = 0.0f;
    // 784 float4 over 256 threads: iterations i, i+256, i+512 (+ tail for tid<16)
    #pragma unroll 4
    for (int i = tid; i < HW4; i += 256) {
        float4 v = px[i];
        acc += (v.x + v.y) + (v.z + v.w);
    }

    // warp reduce
    #pragma unroll
    for (int off = 16; off > 0; off >>= 1)
        acc += __shfl_down_sync(0xFFFFFFFFu, acc, off);

    __shared__ float warp_sums[8];
    if ((tid & 31) == 0) warp_sums[tid >> 5] = acc;
    __syncthreads();

    if (tid < 8) {
        float s = warp_sums[tid];
        #pragma unroll
        for (int off = 4; off > 0; off >>= 1)
            s += __shfl_down_sync(0xFFu, s, off);
        if (tid == 0) g_y[plane] = s * (1.0f / (float)HW);
    }
}

// ---------------------------------------------------------------------------
// Kernel 2: SE MLP + sigmoid + rank-based threshold mask.
// One block per batch row. 256 threads (one per channel).
// Replicates jnp.sort semantics exactly: stable ascending sort position
// = (#values strictly less) + (#equal values at earlier index).
// thresh = value whose sorted position == POSITION-1; mask = s <= thresh.
// Exactly one thread satisfies rank == POSITION-1 (ranks are a permutation),
// so the shared `thresh` is written exactly once.
// ---------------------------------------------------------------------------
__global__ __launch_bounds__(256) void k2_mlp_mask(const float* __restrict__ W1,
                                                   const float* __restrict__ W2) {
    const int b = blockIdx.x;
    const int c = threadIdx.x;

    __shared__ float yrow[C];
    __shared__ float h[R];
    __shared__ float svals[C];
    __shared__ float thresh;

    yrow[c] = g_y[b * C + c];
    __syncthreads();

    // h = relu(y @ W1.T): threads 0..15 each compute one dot of length 256
    if (c < R) {
        const float* __restrict__ w = W1 + c * C;
        float acc = 0.0f;
        #pragma unroll 8
        for (int j = 0; j < C; j++) acc = fmaf(yrow[j], w[j], acc);
        h[c] = fmaxf(acc, 0.0f);
    }
    __syncthreads();

    // s = sigmoid(h @ W2.T): each thread one output channel (dot of length 16)
    const float* __restrict__ w2 = W2 + c * R;
    float acc = 0.0f;
    #pragma unroll
    for (int r = 0; r < R; r++) acc = fmaf(h[r], w2[r], acc);
    const float s = 1.0f / (1.0f + expf(-acc));
    svals[c] = s;
    __syncthreads();

    // O(C) rank computation per thread -> O(C^2) per block (trivial cost)
    int less = 0, eq_before = 0;
    #pragma unroll 8
    for (int j = 0; j < C; j++) {
        float vj = svals[j];
        less += (vj < s) ? 1 : 0;
        eq_before += (vj == s && j < c) ? 1 : 0;
    }
    if (less + eq_before == POSITION - 1) thresh = s;
    __syncthreads();

    g_mask[b * C + c] = (s <= thresh) ? 1.0f : 0.0f;
}

// ---------------------------------------------------------------------------
// Kernel 3: out = x * mask[channel]. One block per plane.
// mask==0 planes: write zeros, skip the x read entirely (saves ~20% read BW).
// ---------------------------------------------------------------------------
__global__ __launch_bounds__(256) void k3_scale(const float* __restrict__ x,
                                                 float* __restrict__ out) {
    const int plane = blockIdx.x;
    const float m = g_mask[plane];
    const size_t base = (size_t)plane * HW;
    const float4* __restrict__ px = reinterpret_cast<const float4*>(x + base);
    float4* __restrict__ po = reinterpret_cast<float4*>(out + base);
    const int tid = threadIdx.x;

    if (m == 0.0f) {
        const float4 z = make_float4(0.f, 0.f, 0.f, 0.f);
        #pragma unroll 4
        for (int i = tid; i < HW4; i += 256) po[i] = z;
    } else {
        #pragma unroll 4
        for (int i = tid; i < HW4; i += 256) po[i] = px[i];
    }
}

// ---------------------------------------------------------------------------
extern "C" void kernel_launch(void* const* d_in, const int* in_sizes, int n_in,
                              void* d_out, int out_size) {
    const float* x  = (const float*)d_in[0];
    const float* W1 = (const float*)d_in[1];
    const float* W2 = (const float*)d_in[2];
    float* out = (float*)d_out;

    k1_gap<<<PLANES, 256>>>(x);
    k2_mlp_mask<<<B, 256>>>(W1, W2);
    k3_scale<<<PLANES, 256>>>(x, out);
}

// round 4
// speedup vs baseline: 1.2021x; 1.2021x over previous
#include <cuda_runtime.h>
#include <math.h>

// Problem constants
#define B 64
#define C 256
#define H 56
#define W 56
#define HW (H * W)          // 3136
#define HW4 (HW / 4)        // 784 float4 per plane
#define R 16                // reduction ratio
#define PLANES (B * C)      // 16384
#define POSITION 205        // round(0.8 * 256)
#define WARPS_PER_BLOCK 8
#define GRID_WP (PLANES / WARPS_PER_BLOCK)   // 2048

// Scratch (allocation-free rule: use __device__ globals)
__device__ float g_y[B * C];      // GAP result
__device__ float g_mask[B * C];   // 0/1 mask

// ---------------------------------------------------------------------------
// Kernel 1: global average pool — WARP per (b,c) plane.
// 2048 blocks x 256 threads (8 warps). Each lane: 24 uniform independent
// float4 loads (deep MLP) + 1 predicated tail load, then one warp shuffle
// reduce. No smem, no barriers.
// ---------------------------------------------------------------------------
__global__ __launch_bounds__(256) void k1_gap(const float* __restrict__ x) {
    const int warp = threadIdx.x >> 5;
    const int lane = threadIdx.x & 31;
    const int plane = blockIdx.x * WARPS_PER_BLOCK + warp;

    const float4* __restrict__ px =
        reinterpret_cast<const float4*>(x + (size_t)plane * HW);

    // 784 = 24*32 + 16: 24 uniform iterations, then lanes 0..15 take the tail.
    float acc = 0.0f;
    #pragma unroll 8
    for (int k = 0; k < 24; k++) {
        float4 v = px[k * 32 + lane];
        acc += (v.x + v.y) + (v.z + v.w);
    }
    if (lane < 16) {
        float4 v = px[24 * 32 + lane];
        acc += (v.x + v.y) + (v.z + v.w);
    }

    #pragma unroll
    for (int off = 16; off > 0; off >>= 1)
        acc += __shfl_down_sync(0xFFFFFFFFu, acc, off);

    if (lane == 0) g_y[plane] = acc * (1.0f / (float)HW);
}

// ---------------------------------------------------------------------------
// Kernel 2: SE MLP + sigmoid + rank-based threshold mask.
// One block per batch row, 256 threads (8 warps).
// GEMV1 parallelized: warp w computes h[w] and h[w+8] via warp-reduced dots.
// Rank semantics replicate jnp.sort exactly (stable ascending):
// rank = #strictly-less + #equal-at-earlier-index; exactly one thread has
// rank == POSITION-1, so `thresh` is written exactly once.
// ---------------------------------------------------------------------------
__global__ __launch_bounds__(256) void k2_mlp_mask(const float* __restrict__ W1,
                                                   const float* __restrict__ W2) {
    const int b = blockIdx.x;
    const int c = threadIdx.x;
    const int warp = c >> 5;
    const int lane = c & 31;

    __shared__ float yrow[C];
    __shared__ float h[R];
    __shared__ float svals[C];
    __shared__ float thresh;

    yrow[c] = g_y[b * C + c];
    __syncthreads();

    // h = relu(y @ W1.T): warp w handles hidden units w and w+8
    #pragma unroll
    for (int t = 0; t < 2; t++) {
        const int r = warp + t * 8;
        const float* __restrict__ w = W1 + r * C;
        float acc = 0.0f;
        #pragma unroll
        for (int j = lane; j < C; j += 32) acc = fmaf(yrow[j], w[j], acc);
        #pragma unroll
        for (int off = 16; off > 0; off >>= 1)
            acc += __shfl_down_sync(0xFFFFFFFFu, acc, off);
        if (lane == 0) h[r] = fmaxf(acc, 0.0f);
    }
    __syncthreads();

    // s = sigmoid(h @ W2.T): each thread one output channel (dot of length 16)
    const float* __restrict__ w2 = W2 + c * R;
    float acc = 0.0f;
    #pragma unroll
    for (int r = 0; r < R; r++) acc = fmaf(h[r], w2[r], acc);
    const float s = 1.0f / (1.0f + expf(-acc));
    svals[c] = s;
    __syncthreads();

    // O(C) rank computation per thread
    int less = 0, eq_before = 0;
    #pragma unroll 8
    for (int j = 0; j < C; j++) {
        float vj = svals[j];
        less += (vj < s) ? 1 : 0;
        eq_before += (vj == s && j < c) ? 1 : 0;
    }
    if (less + eq_before == POSITION - 1) thresh = s;
    __syncthreads();

    g_mask[b * C + c] = (s <= thresh) ? 1.0f : 0.0f;
}

// ---------------------------------------------------------------------------
// Kernel 3: out = x * mask[channel] — WARP per plane, REVERSED plane order.
// High planes were read last by K1, so they sit in L2 when K3 starts;
// reading them first converts up to ~100MB of DRAM reads into L2 hits.
// Streaming stores (__stcs) keep output writes from evicting those lines.
// mask==0 planes: write zeros, skip the x read entirely.
// ---------------------------------------------------------------------------
__global__ __launch_bounds__(256) void k3_scale(const float* __restrict__ x,
                                                 float* __restrict__ out) {
    const int warp = threadIdx.x >> 5;
    const int lane = threadIdx.x & 31;
    const int plane = (PLANES - 1) - (blockIdx.x * WARPS_PER_BLOCK + warp);

    const float m = g_mask[plane];
    const size_t base = (size_t)plane * HW;
    const float4* __restrict__ px = reinterpret_cast<const float4*>(x + base);
    float4* __restrict__ po = reinterpret_cast<float4*>(out + base);

    if (m == 0.0f) {
        const float4 z = make_float4(0.f, 0.f, 0.f, 0.f);
        #pragma unroll 8
        for (int k = 0; k < 24; k++) __stcs(&po[k * 32 + lane], z);
        if (lane < 16) __stcs(&po[24 * 32 + lane], z);
    } else {
        #pragma unroll 8
        for (int k = 0; k < 24; k++) {
            float4 v = px[k * 32 + lane];
            __stcs(&po[k * 32 + lane], v);
        }
        if (lane < 16) {
            float4 v = px[24 * 32 + lane];
            __stcs(&po[24 * 32 + lane], v);
        }
    }
}

// ---------------------------------------------------------------------------
extern "C" void kernel_launch(void* const* d_in, const int* in_sizes, int n_in,
                              void* d_out, int out_size) {
    const float* x  = (const float*)d_in[0];
    const float* W1 = (const float*)d_in[1];
    const float* W2 = (const float*)d_in[2];
    float* out = (float*)d_out;

    k1_gap<<<GRID_WP, 256>>>(x);
    k2_mlp_mask<<<B, 256>>>(W1, W2);
    k3_scale<<<GRID_WP, 256>>>(x, out);
}